// round 1
// baseline (speedup 1.0000x reference)
#include <cuda_runtime.h>
#include <cstddef>

// Problem constants
#define Bn   16
#define Cn   256
#define Hn   64
#define Wn   64
#define PP   81          // 9x9 displacements
#define MAXD 4

// Tiling
#define TILE_I 8         // rows per block
#define CC     8         // channel chunk in smem
#define YROWS  10        // TILE_I + 2 (rows needed for one 3-di pass)
#define YCOLS  72        // 64 + 2*4 halo
#define NTHREADS 128

__global__ __launch_bounds__(NTHREADS, 2)
void corr_kernel(const float* __restrict__ x,
                 const float* __restrict__ y,
                 float* __restrict__ out)
{
    // grid: (row_tiles=8, batch=16, pass=3)
    const int i0   = blockIdx.x * TILE_I;
    const int b    = blockIdx.y;
    const int d0   = blockIdx.z * 3;       // di in {d0, d0+1, d0+2}

    const int tid = threadIdx.x;
    const int tc  = tid & 31;              // 0..31 -> pixel cols 2tc, 2tc+1
    const int tr  = tid >> 5;              // 0..3  -> pixel rows i0+2tr, i0+2tr+1

    __shared__ float sx[CC][TILE_I][Wn];       // 8*8*64*4  = 16 KB
    __shared__ float sy[CC][YROWS][YCOLS];     // 8*10*72*4 = 23.04 KB

    float acc[3][9][2][2];
    #pragma unroll
    for (int a = 0; a < 3; a++)
        #pragma unroll
        for (int d = 0; d < 9; d++)
            #pragma unroll
            for (int p = 0; p < 2; p++) {
                acc[a][d][p][0] = 0.f;
                acc[a][d][p][1] = 0.f;
            }

    const float* xb = x + (size_t)b * Cn * (Hn * Wn);
    const float* yb = y + (size_t)b * Cn * (Hn * Wn);

    const int yrow0 = i0 + d0 - MAXD;      // global row corresponding to sy row 0

    for (int c0 = 0; c0 < Cn; c0 += CC) {
        __syncthreads();

        // ---- load x chunk: contiguous copy, vectorized float4 ----
        // each channel: rows i0..i0+7 are 512 contiguous floats = 128 float4
        {
            const float4* xg = (const float4*)(xb + (size_t)c0 * (Hn * Wn) + i0 * Wn);
            float4* xs = (float4*)&sx[0][0][0];
            #pragma unroll
            for (int k = 0; k < (CC * TILE_I * Wn / 4) / NTHREADS; k++) {
                int idx = k * NTHREADS + tid;                 // 0..255
                int cc  = idx >> 7;                           // /128
                int off = idx & 127;
                xs[idx] = xg[(size_t)cc * (Hn * Wn / 4) + off];
            }
        }

        // ---- load y chunk with zero-padded halo ----
        for (int idx = tid; idx < CC * YROWS * YCOLS; idx += NTHREADS) {
            int cc   = idx / (YROWS * YCOLS);
            int rem  = idx - cc * (YROWS * YCOLS);
            int r    = rem / YCOLS;
            int col  = rem - r * YCOLS;
            int gr   = yrow0 + r;
            int gcol = col - MAXD;
            float v = 0.f;
            if (gr >= 0 && gr < Hn && gcol >= 0 && gcol < Wn)
                v = yb[(size_t)(c0 + cc) * (Hn * Wn) + gr * Wn + gcol];
            sy[cc][r][col] = v;
        }
        __syncthreads();

        #pragma unroll 1
        for (int cc = 0; cc < CC; cc++) {
            // x values for this thread's 2x2 pixel tile
            float xv[2][2];
            #pragma unroll
            for (int pl = 0; pl < 2; pl++) {
                float2 v = *(const float2*)&sx[cc][2 * tr + pl][2 * tc];
                xv[pl][0] = v.x; xv[pl][1] = v.y;
            }
            // y rows: smem row = 2*tr + (pl + dl), yr = pl+dl in 0..3
            #pragma unroll
            for (int yr = 0; yr < 4; yr++) {
                float yv[10];
                #pragma unroll
                for (int k = 0; k < 5; k++) {
                    float2 v = *(const float2*)&sy[cc][2 * tr + yr][2 * tc + 2 * k];
                    yv[2 * k]     = v.x;
                    yv[2 * k + 1] = v.y;
                }
                #pragma unroll
                for (int pl = 0; pl < 2; pl++) {
                    const int dl = yr - pl;            // compile-time after unroll
                    if (dl >= 0 && dl < 3) {
                        #pragma unroll
                        for (int dj = 0; dj < 9; dj++) {
                            acc[dl][dj][pl][0] += xv[pl][0] * yv[dj];
                            acc[dl][dj][pl][1] += xv[pl][1] * yv[dj + 1];
                        }
                    }
                }
            }
        }
    }

    // ---- write out: each output element owned by exactly one thread ----
    const float scale = 1.f / (float)Cn;
    #pragma unroll
    for (int dl = 0; dl < 3; dl++) {
        #pragma unroll
        for (int dj = 0; dj < 9; dj++) {
            const int p = (d0 + dl) * 9 + dj;
            #pragma unroll
            for (int pl = 0; pl < 2; pl++) {
                const int row = i0 + 2 * tr + pl;
                const int col = 2 * tc;
                float2 v;
                v.x = acc[dl][dj][pl][0] * scale;
                v.y = acc[dl][dj][pl][1] * scale;
                *(float2*)&out[(((size_t)b * PP + p) * Hn + row) * Wn + col] = v;
            }
        }
    }
}

extern "C" void kernel_launch(void* const* d_in, const int* in_sizes, int n_in,
                              void* d_out, int out_size)
{
    const float* x = (const float*)d_in[0];
    const float* y = (const float*)d_in[1];
    float* out = (float*)d_out;

    dim3 grid(Hn / TILE_I, Bn, 3);   // 8 x 16 x 3 = 384 blocks
    dim3 block(NTHREADS);
    corr_kernel<<<grid, block>>>(x, y, out);
}

// round 5
// speedup vs baseline: 3.7117x; 3.7117x over previous
#include <cuda_runtime.h>
#include <cstdint>
#include <cstddef>

#define Bn 16
#define Cn 256
#define Hn 64
#define Wn 64
#define MAXD 4
#define PP 81

#define TILE_I 8
#define CC 8
#define NCHUNK (Cn / CC)        // 32
#define YROWS 10                // TILE_I + 2 (3 di per pass)
#define YCOLS 72                // 64 + 2*4 halo
#define NT 256

#define SY_ELEMS (CC * YROWS * YCOLS)   // 5760
#define SX_ELEMS (CC * TILE_I * Wn)     // 4096
#define SY_BYTES (SY_ELEMS * 4)         // 23040
#define SX_BYTES (SX_ELEMS * 4)         // 16384
#define BUF_BYTES (SY_BYTES + SX_BYTES) // 39424
#define SMEM_TOTAL (2 * BUF_BYTES)      // 78848
#define BUF_FLOATS (BUF_BYTES / 4)

__device__ __forceinline__ void cp16(uint32_t dst, const void* src) {
    asm volatile("cp.async.cg.shared.global [%0], [%1], 16;\n"
                 :: "r"(dst), "l"(src));
}
__device__ __forceinline__ void cp_commit() {
    asm volatile("cp.async.commit_group;\n" ::: "memory");
}
__device__ __forceinline__ void cp_wait1() {
    asm volatile("cp.async.wait_group 1;\n" ::: "memory");
}
__device__ __forceinline__ void cp_wait0() {
    asm volatile("cp.async.wait_group 0;\n" ::: "memory");
}

__global__ __launch_bounds__(NT, 2)
void corr_kernel(const float* __restrict__ x,
                 const float* __restrict__ y,
                 float* __restrict__ out)
{
    extern __shared__ float smem[];

    const int tid  = threadIdx.x;
    const int lane = tid & 31;          // pixel cols 2*lane, 2*lane+1
    const int tr   = tid >> 5;          // pixel row within tile (warp id), 0..7
    const int i0   = blockIdx.x * TILE_I;
    const int b    = blockIdx.y;
    const int d0   = blockIdx.z * 3;    // di in {d0, d0+1, d0+2}
    const int yrow0 = i0 + d0 - MAXD;   // global row for sy row 0

    const float* xb = x + (size_t)b * Cn * (Hn * Wn);
    const float* yb = y + (size_t)b * Cn * (Hn * Wn);

    const uint32_t sbase = (uint32_t)__cvta_generic_to_shared(smem);

    // ---- zero both buffers once (halo cols + OOB rows stay zero forever) ----
    {
        float4* s4 = (float4*)smem;
        for (int idx = tid; idx < SMEM_TOTAL / 16; idx += NT)
            s4[idx] = make_float4(0.f, 0.f, 0.f, 0.f);
    }
    __syncthreads();

    // ---- loader thread mapping (constant per thread) ----
    const int y_cc = (tid >> 4) & 7;    // channel-in-chunk for y loads
    const int y_q  = tid & 15;          // float4 index within row
    const int y_rh = tid >> 7;          // row half (0/1)
    // x loads handled with computed idx per iteration (shifts only)

    float acc[3][9][2];
    #pragma unroll
    for (int dl = 0; dl < 3; dl++)
        #pragma unroll
        for (int dj = 0; dj < 9; dj++) {
            acc[dl][dj][0] = 0.f;
            acc[dl][dj][1] = 0.f;
        }

    // ---- issue chunk k's loads into buffer (k&1) ----
    auto issue = [&](int k) {
        const uint32_t syb = sbase + (uint32_t)(k & 1) * BUF_BYTES;
        const uint32_t sxb = syb + SY_BYTES;
        // y: 2 rows per iteration, 5 iterations = 10 rows
        #pragma unroll
        for (int m = 0; m < 5; m++) {
            const int r  = 2 * m + y_rh;
            const int gr = yrow0 + r;
            if ((unsigned)gr < (unsigned)Hn) {
                const float* src = yb + (size_t)(k * CC + y_cc) * (Hn * Wn)
                                      + gr * Wn + y_q * 4;
                const uint32_t dst = syb +
                    (uint32_t)(((y_cc * YROWS + r) * YCOLS + 4 + y_q * 4) * 4);
                cp16(dst, src);
            }
        }
        // x: 1024 float4s, 4 per thread
        #pragma unroll
        for (int m = 0; m < 4; m++) {
            const int idx = tid + NT * m;
            const int cc  = idx >> 7;
            const int rem = idx & 127;
            const int r   = rem >> 4;
            const int qq  = rem & 15;
            const float* src = xb + (size_t)(k * CC + cc) * (Hn * Wn)
                                  + (i0 + r) * Wn + qq * 4;
            const uint32_t dst = sxb +
                (uint32_t)(((cc * TILE_I + r) * Wn + qq * 4) * 4);
            cp16(dst, src);
        }
        cp_commit();
    };

    // ---- pipelined main loop ----
    issue(0);
    #pragma unroll 1
    for (int k = 0; k < NCHUNK; k++) {
        if (k + 1 < NCHUNK) {
            issue(k + 1);       // buf (k+1)&1: last read by compute(k-1), sync'd
            cp_wait1();         // chunk k's group complete
        } else {
            cp_wait0();
        }
        __syncthreads();

        // ---- compute chunk k from buffer (k&1) ----
        const int bufo = (k & 1) * BUF_FLOATS;
        const int syo  = bufo;
        const int sxo  = bufo + SY_BYTES / 4;

        #pragma unroll 1
        for (int cc = 0; cc < CC; cc++) {
            const float2 xv = *(const float2*)
                &smem[sxo + (cc * TILE_I + tr) * Wn + 2 * lane];
            #pragma unroll
            for (int dl = 0; dl < 3; dl++) {
                float yv[10];
                const int rbase = syo + (cc * YROWS + tr + dl) * YCOLS + 2 * lane;
                #pragma unroll
                for (int kk = 0; kk < 5; kk++) {
                    const float2 v = *(const float2*)&smem[rbase + 2 * kk];
                    yv[2 * kk]     = v.x;
                    yv[2 * kk + 1] = v.y;
                }
                #pragma unroll
                for (int dj = 0; dj < 9; dj++) {
                    acc[dl][dj][0] += xv.x * yv[dj];
                    acc[dl][dj][1] += xv.y * yv[dj + 1];
                }
            }
        }
        __syncthreads();        // protect buffer (k&1) before issue(k+2)
    }

    // ---- write out ----
    const float scale = 1.f / (float)Cn;
    const int row = i0 + tr;
    #pragma unroll
    for (int dl = 0; dl < 3; dl++)
        #pragma unroll
        for (int dj = 0; dj < 9; dj++) {
            const int p = (d0 + dl) * 9 + dj;
            float2 v;
            v.x = acc[dl][dj][0] * scale;
            v.y = acc[dl][dj][1] * scale;
            *(float2*)&out[(((size_t)b * PP + p) * Hn + row) * Wn + 2 * lane] = v;
        }
}

extern "C" void kernel_launch(void* const* d_in, const int* in_sizes, int n_in,
                              void* d_out, int out_size)
{
    const float* x = (const float*)d_in[0];
    const float* y = (const float*)d_in[1];
    float* out = (float*)d_out;

    cudaFuncSetAttribute(corr_kernel,
                         cudaFuncAttributeMaxDynamicSharedMemorySize,
                         SMEM_TOTAL);

    dim3 grid(Hn / TILE_I, Bn, 3);   // 8 x 16 x 3 = 384 blocks
    dim3 block(NT);
    corr_kernel<<<grid, block, SMEM_TOTAL>>>(x, y, out);
}